// round 4
// baseline (speedup 1.0000x reference)
#include <cuda_runtime.h>
#include <math.h>

#define NB 16
#define NT 2048
#define ND 512
#define NH 512
#define SIXH 3072
#define MROWS (NB * NT)   // 32768

#define GRID2 128
#define THR2 256
// smem: sh_h 512*16 | sh_wt 512*48 (dup-pair) | red 1440 u64 (=2880 f)
#define SMEM2_FLOATS (8192 + 24576 + 2880)
#define SMEM2_BYTES (SMEM2_FLOATS * 4)

typedef unsigned long long u64;

// ---------------- device scratch (static: no runtime allocation) ----------------
__device__ float g_pi[(size_t)MROWS * SIXH];          // 402 MB: PI = X @ W^T + b
__device__ float g_ht[2][NH * NB];                    // h double buffer, layout [k][b]
__device__ unsigned long long g_bar_count;            // monotonic grid-barrier counter

// ---------------- packed f32x2 helpers (SASS FFMA2 — exact fp32 numerics) -------
__device__ __forceinline__ u64 pack2(float lo, float hi) {
    u64 r;
    asm("mov.b64 %0, {%1, %2};" : "=l"(r) : "f"(lo), "f"(hi));
    return r;
}
__device__ __forceinline__ void unpack2(u64 v, float& lo, float& hi) {
    asm("mov.b64 {%0, %1}, %2;" : "=f"(lo), "=f"(hi) : "l"(v));
}
__device__ __forceinline__ void fma2(u64& d, u64 a, u64 b) {
    asm("fma.rn.f32x2 %0, %1, %2, %0;" : "+l"(d) : "l"(a), "l"(b));
}

// ---------------- math helpers ----------------
__device__ __forceinline__ float sigf(float x) {
    return 1.0f / (1.0f + __expf(-x));
}
__device__ __forceinline__ float tanh_acc(float x) {
    float e = __expf(-2.0f * fabsf(x));
    float t = (1.0f - e) / (1.0f + e);
    return x >= 0.0f ? t : -t;
}

// =====================================================================
// Phase 1: PI[m][n] = sum_k X[m][k] * W[n][k] + bias[n]
// Tiles: 128x128, BK=16, 256 threads, 8x8 microtile as 8x4 FFMA2.
// Near fp32 roofline (~1.5ms chip floor) — unchanged this round.
// =====================================================================
#define BK1 16
#define LDA1 132

__global__ void __launch_bounds__(256) gemm_pi_kernel(
    const float* __restrict__ X, const float* __restrict__ W,
    const float* __restrict__ bias)
{
    __shared__ float As[BK1 * LDA1];
    __shared__ float Bs[BK1 * LDA1];

    const int tid = threadIdx.x;
    const int tx = tid & 15, ty = tid >> 4;
    const int n0 = blockIdx.x * 128;
    const int m0 = blockIdx.y * 128;

    const float* Xp = X + (size_t)m0 * ND;
    const float* Wp = W + (size_t)n0 * ND;

    u64 accP[8][4];
#pragma unroll
    for (int i = 0; i < 8; i++)
#pragma unroll
        for (int j = 0; j < 4; j++) accP[i][j] = 0ULL;

    for (int kc = 0; kc < ND; kc += BK1) {
#pragma unroll
        for (int i = 0; i < 2; i++) {
            int idx4 = tid + 256 * i;
            int row = idx4 >> 2;
            int kq = idx4 & 3;
            float4 va = *(const float4*)(Xp + (size_t)row * ND + kc + kq * 4);
            float4 vb = *(const float4*)(Wp + (size_t)row * ND + kc + kq * 4);
            As[(kq * 4 + 0) * LDA1 + row] = va.x;
            As[(kq * 4 + 1) * LDA1 + row] = va.y;
            As[(kq * 4 + 2) * LDA1 + row] = va.z;
            As[(kq * 4 + 3) * LDA1 + row] = va.w;
            Bs[(kq * 4 + 0) * LDA1 + row] = vb.x;
            Bs[(kq * 4 + 1) * LDA1 + row] = vb.y;
            Bs[(kq * 4 + 2) * LDA1 + row] = vb.z;
            Bs[(kq * 4 + 3) * LDA1 + row] = vb.w;
        }
        __syncthreads();

#pragma unroll
        for (int k = 0; k < BK1; k++) {
            float a[8];
            *(float4*)&a[0] = *(const float4*)&As[k * LDA1 + ty * 8];
            *(float4*)&a[4] = *(const float4*)&As[k * LDA1 + ty * 8 + 4];
            ulonglong2 b01 = *(const ulonglong2*)&Bs[k * LDA1 + tx * 8];
            ulonglong2 b23 = *(const ulonglong2*)&Bs[k * LDA1 + tx * 8 + 4];
#pragma unroll
            for (int i = 0; i < 8; i++) {
                u64 ad = pack2(a[i], a[i]);
                fma2(accP[i][0], b01.x, ad);
                fma2(accP[i][1], b01.y, ad);
                fma2(accP[i][2], b23.x, ad);
                fma2(accP[i][3], b23.y, ad);
            }
        }
        __syncthreads();
    }

    float bv[8];
#pragma unroll
    for (int j = 0; j < 8; j++) bv[j] = bias[n0 + tx * 8 + j];

#pragma unroll
    for (int i = 0; i < 8; i++) {
        float c[8];
#pragma unroll
        for (int jp = 0; jp < 4; jp++)
            unpack2(accP[i][jp], c[2 * jp], c[2 * jp + 1]);
        size_t m = (size_t)m0 + ty * 8 + i;
        float* op = g_pi + m * SIXH + n0 + tx * 8;
        float4 r0 = make_float4(c[0] + bv[0], c[1] + bv[1],
                                c[2] + bv[2], c[3] + bv[3]);
        float4 r1 = make_float4(c[4] + bv[4], c[5] + bv[5],
                                c[6] + bv[6], c[7] + bv[7]);
        *(float4*)op = r0;
        *(float4*)(op + 4) = r1;
    }
}

// =====================================================================
// Grid barrier: monotonic counter (replay-safe), release-atomic arrival.
// Reader-side __threadfence is REQUIRED: gpu-scope fence emits CCTL.IVALL
// which invalidates L1D — without it the h reloads can hit stale L1 lines.
// =====================================================================
__device__ unsigned long long* bar_addr();
__device__ __forceinline__ void grid_barrier() {
    __syncthreads();
    if (threadIdx.x == 0) {
        unsigned long long arrive;
        asm volatile("atom.release.gpu.global.add.u64 %0, [%1], 1;"
                     : "=l"(arrive) : "l"(&g_bar_count) : "memory");
        unsigned long long target = (arrive / GRID2 + 1ULL) * GRID2;
        if (arrive + 1ULL != target) {
            volatile unsigned long long* p =
                (volatile unsigned long long*)&g_bar_count;
            while (*p < target) { }
        }
        __threadfence();   // acquire + L1D invalidate
    }
    __syncthreads();
}

// =====================================================================
// Phase 2: persistent recurrence, latency-trimmed.
// W held in SMEM as duplicated pairs: sh_wt[k][jg*12 + g*2 + {0,1}] both
// equal W[g*NH + jo][k]. Inner loop: 1 LDS.64 (h-pair {b0,b1}) +
// 2 LDS.128 + 1 LDS.64 (w dup-pairs) + 5 FFMA2 = 9 instrs / 10 FMAs,
// accumulators are {b0,b1} pairs -> 5 STS.64 partials.
// PI prefetch for t+1 issued BEFORE the barrier (hidden under the spin).
// =====================================================================
__global__ void __launch_bounds__(THR2, 1) lstm_rec_kernel(
    const float* __restrict__ W, const float* __restrict__ bias,
    const int* __restrict__ lengths, float* __restrict__ out)
{
    extern __shared__ float smem[];
    float* sh_h  = smem;                   // [512][16]  k-major
    float* sh_wt = smem + 8192;            // [512][48]  dup-pair layout
    u64*   red   = (u64*)(smem + 8192 + 24576);  // [8bg][5g][4jg][9] u64

    const int tid = threadIdx.x;
    const int cta = blockIdx.x;
    const int jo_base = cta * 4;

    // --- build persistent duplicated W slice (once) ---
    for (int p = tid; p < 20 * 512; p += THR2) {
        int k = p & 511;
        int r = p >> 9;          // 0..19
        int g = r >> 2;          // gate
        int jg = r & 3;          // channel offset
        float v = W[(size_t)(g * NH + jo_base + jg) * ND + k];
        int base = k * 48 + jg * 12 + g * 2;
        sh_wt[base] = v;
        sh_wt[base + 1] = v;
    }

    // --- combine-thread persistent state ---
    int b_c = 0, jo_c = 0, len_c = 0;
    float bias5[5] = {0, 0, 0, 0, 0};
    float c_reg = 0.0f;
    const float* pi_row = g_pi;
    if (tid < 64) {
        b_c = tid >> 2;
        jo_c = jo_base + (tid & 3);
#pragma unroll
        for (int g = 0; g < 5; g++) bias5[g] = bias[g * NH + jo_c];
        len_c = lengths[b_c];
        pi_row = g_pi + (size_t)b_c * NT * SIXH + jo_c;
    }

    // --- zero h buffer 0 ---
    if (tid < 64) g_ht[0][cta * 64 + tid] = 0.0f;

    // prefetch PI(t=0)
    float pi5[5] = {0, 0, 0, 0, 0}, pi6 = 0.0f;
    if (tid < 64) {
#pragma unroll
        for (int g = 0; g < 5; g++) pi5[g] = pi_row[g * NH];
        pi6 = pi_row[5 * NH];
    }
    grid_barrier();

    const int warp = tid >> 5, lane = tid & 31;
    const int bg = lane & 7;   // batch pair {2bg, 2bg+1}
    const int jg = lane >> 3;  // channel offset within CTA
    const u64*   hp0 = (const u64*)sh_h + (size_t)warp * 64 * 8 + bg;
    const float* wp0 = sh_wt + (size_t)warp * 64 * 48 + jg * 12;

    for (int t = 0; t < NT; t++) {
        const float* hbuf = g_ht[t & 1];
        float* hnext = g_ht[(t & 1) ^ 1];

        // stage h (already [k][b]) -> straight coalesced copy
#pragma unroll
        for (int i = 0; i < 8; i++) {
            int off = tid * 4 + i * 1024;
            *(float4*)&sh_h[off] = *(const float4*)&hbuf[off];
        }
        __syncthreads();

        // --- K-split packed GEMM: {b0,b1} x 5 gates per lane, 64 k ---
        u64 acc0 = 0, acc1 = 0, acc2 = 0, acc3 = 0, acc4 = 0;
        {
            const u64* hp = hp0;
            const float* wp = wp0;
#pragma unroll 8
            for (int kk = 0; kk < 64; kk++) {
                u64 hd = *hp;                                  // {h_b0, h_b1}
                ulonglong2 w01 = *(const ulonglong2*)wp;       // {w0,w0},{w1,w1}
                ulonglong2 w23 = *(const ulonglong2*)(wp + 4); // {w2,w2},{w3,w3}
                u64 w44 = *(const u64*)(wp + 8);               // {w4,w4}
                fma2(acc0, hd, w01.x);
                fma2(acc1, hd, w01.y);
                fma2(acc2, hd, w23.x);
                fma2(acc3, hd, w23.y);
                fma2(acc4, hd, w44);
                hp += 8;
                wp += 48;
            }
        }

        // write pair partials: red[((bg*5+g)*4+jg)*9 + warp]
        {
            int rb = (bg * 5) * 4 + jg;
            red[(rb + 0) * 9 + warp] = acc0;
            red[(rb + 4) * 9 + warp] = acc1;
            red[(rb + 8) * 9 + warp] = acc2;
            red[(rb + 12) * 9 + warp] = acc3;
            red[(rb + 16) * 9 + warp] = acc4;
        }
        __syncthreads();

        // --- reduce across 8 warps + gate math (64 threads) ---
        if (tid < 64) {
            const float* redf = (const float*)red;
            int bgc = b_c >> 1, e = b_c & 1, q = tid & 3;
            float gv[5];
#pragma unroll
            for (int g = 0; g < 5; g++) {
                const float* rp = redf + (((bgc * 5 + g) * 4 + q) * 9) * 2 + e;
                float s = ((rp[0] + rp[2]) + (rp[4] + rp[6])) +
                          ((rp[8] + rp[10]) + (rp[12] + rp[14]));
                gv[g] = s + bias5[g] + pi5[g];
            }
            float ig = sigf(gv[0]);
            float fg = sigf(gv[1]);
            float mi = tanh_acc(gv[2]);
            float og = sigf(gv[3]);
            float hwg = sigf(gv[4]);
            float mem = fmaf(ig, mi, fg * c_reg);
            float o_ = og * tanh_acc(mem);
            o_ = fmaf(hwg, o_ - pi6, pi6);
            if (t >= len_c) { o_ = 0.0f; mem = 0.0f; }
            c_reg = mem;

            hnext[jo_c * 16 + b_c] = o_;   // transposed for next step
            out[((size_t)b_c * NT + t) * NH + jo_c] = o_;

            // prefetch PI(t+1) now: latency hides under the barrier spin
            if (t + 1 < NT) {
                const float* pr = pi_row + (size_t)(t + 1) * SIXH;
#pragma unroll
                for (int g = 0; g < 5; g++) pi5[g] = pr[g * NH];
                pi6 = pr[5 * NH];
            }
        }
        grid_barrier();
    }
}

// =====================================================================
// launch
// =====================================================================
extern "C" void kernel_launch(void* const* d_in, const int* in_sizes, int n_in,
                              void* d_out, int out_size) {
    const float* x = (const float*)d_in[0];
    const int* lengths = (const int*)d_in[1];
    const float* W = (const float*)d_in[2];
    const float* bias = (const float*)d_in[3];
    float* out = (float*)d_out;

    static bool attr_done = false;
    if (!attr_done) {
        cudaFuncSetAttribute(lstm_rec_kernel,
                             cudaFuncAttributeMaxDynamicSharedMemorySize,
                             SMEM2_BYTES);
        attr_done = true;
    }

    dim3 g1(SIXH / 128, MROWS / 128);  // (24, 256)
    gemm_pi_kernel<<<g1, 256>>>(x, W, bias);
    lstm_rec_kernel<<<GRID2, THR2, SMEM2_BYTES>>>(W, bias, lengths, out);
}